// round 7
// baseline (speedup 1.0000x reference)
#include <cuda_runtime.h>
#include <cuda_bf16.h>
#include <cuda_fp16.h>

#define NN 100000
#define NE 3200000
#define HID 36
#define NH 3
#define HD 12
#define FEH 48           // packed fp16 row stride in halves: 36 feat + 3 el + pad = 96B
#define ACC_S 40         // g_acc row stride: 36 acc + 3 den + pad (160B)
#define FULL 0xffffffffu

// ---- persistent scratch ----
__device__ __align__(128) __half g_fe[NN * FEH];  // fp16: [0..35] feat, [36..38] el
__device__ float g_er[NN * NH];
__device__ float g_rst[NN * HID];    // fp32: x + bias
__device__ __align__(128) float g_acc[NN * ACC_S]; // gather partials (zero-init, consumers re-zero)
__device__ int   g_deg[NN];          // zero-init; out_proj re-zeroes for next call
__device__ int   g_off[NN];
__device__ int   g_end[NN];
__device__ int   g_cursor[NN];
__device__ int   g_esrc[NE];
__device__ int   g_total;            // zero-init; out_proj re-zeroes

__device__ __forceinline__ unsigned pack2(float a, float b) {
    __half2 h = __floats2half2_rn(a, b);
    return *reinterpret_cast<unsigned*>(&h);
}

__device__ __forceinline__ void red_add_v4(float* gaddr, float a, float b, float c, float d) {
    unsigned long long p = __cvta_generic_to_global(gaddr);
    asm volatile("red.global.add.v4.f32 [%0], {%1, %2, %3, %4};"
                 :: "l"(p), "f"(a), "f"(b), "f"(c), "f"(d) : "memory");
}

// ============================================================================
// Launch 0: fused node_prep<layer0> (blocks [0,np_blocks)) + hist (rest).
// ============================================================================
__global__ __launch_bounds__(256)
void prep0_hist(const float* __restrict__ in,
                const float* __restrict__ lin0_w, const float* __restrict__ lin0_b,
                const float* __restrict__ fc_w,
                const float* __restrict__ a_l, const float* __restrict__ a_r,
                const float* __restrict__ bias,
                const int* __restrict__ dst,
                int n_nodes, int ne, int np_blocks) {
    if (blockIdx.x >= np_blocks) {
        // ---- hist branch: grid-stride over edges, 4 per iter ----
        int bid = blockIdx.x - np_blocks;
        int nb  = gridDim.x - np_blocks;
        int tid = bid * 256 + threadIdx.x;
        int stride = nb * 256;
        int nv = ne >> 2;
        const int4* d4 = reinterpret_cast<const int4*>(dst);
        for (int i = tid; i < nv; i += stride) {
            int4 d = __ldg(&d4[i]);
            atomicAdd(&g_deg[d.x], 1);
            atomicAdd(&g_deg[d.y], 1);
            atomicAdd(&g_deg[d.z], 1);
            atomicAdd(&g_deg[d.w], 1);
        }
        for (int i = (nv << 2) + tid; i < ne; i += stride)
            atomicAdd(&g_deg[dst[i]], 1);
        return;
    }

    // ---- node_prep layer 0 ----
    __shared__ float sW[HID * HID];
    __shared__ float sW0[HID * HID];
    __shared__ float sAl[HID], sAr[HID], sB[HID], sB0[HID];

    int tid = threadIdx.x;
    for (int i = tid; i < HID * HID; i += 256) {
        sW[i]  = fc_w[i];
        sW0[i] = lin0_w[i];
    }
    if (tid < HID) {
        sAl[tid] = a_l[tid];
        sAr[tid] = a_r[tid];
        sB[tid]  = bias[tid];
        sB0[tid] = lin0_b[tid];
    }
    __syncthreads();

    int n = blockIdx.x * 256 + tid;
    if (n >= n_nodes) return;

    float nf[HID], x[HID];
#pragma unroll
    for (int k = 0; k < HID; k++) nf[k] = in[n * HID + k];
#pragma unroll
    for (int j = 0; j < HID; j++) {
        float a = sB0[j];
#pragma unroll
        for (int k = 0; k < HID; k++) a += nf[k] * sW0[k * HID + j];
        x[j] = a;
    }

    float f[HID];
#pragma unroll
    for (int j = 0; j < HID; j++) {
        float a = 0.f;
#pragma unroll
        for (int k = 0; k < HID; k++) a += x[k] * sW[k * HID + j];
        f[j] = a;
    }

#pragma unroll
    for (int j = 0; j < HID; j++)
        g_rst[n * HID + j] = x[j] + sB[j];

    float el[NH];
#pragma unroll
    for (int h = 0; h < NH; h++) {
        float l = 0.f, r = 0.f;
#pragma unroll
        for (int d = 0; d < HD; d++) {
            l += f[h * HD + d] * sAl[h * HD + d];
            r += f[h * HD + d] * sAr[h * HD + d];
        }
        el[h] = l;
        g_er[n * NH + h] = r;
    }

    unsigned u[20];
#pragma unroll
    for (int i = 0; i < 18; i++) u[i] = pack2(f[2 * i], f[2 * i + 1]);
    u[18] = pack2(el[0], el[1]);
    u[19] = pack2(el[2], 0.f);
    uint4* dp = reinterpret_cast<uint4*>(g_fe + n * FEH);
#pragma unroll
    for (int i = 0; i < 5; i++)
        dp[i] = make_uint4(u[4 * i], u[4 * i + 1], u[4 * i + 2], u[4 * i + 3]);
}

// ============================================================================
// Launch 1: single-pass scan (atomic block base). Ranges need not be in node
// order — gather uses g_off/g_end per node.
// ============================================================================
__global__ __launch_bounds__(256)
void scan_fused(int n) {
    __shared__ int sh[256];
    __shared__ int sbase;
    int t = threadIdx.x;
    int i = blockIdx.x * 256 + t;
    int v = (i < n) ? g_deg[i] : 0;
    sh[t] = v;
    __syncthreads();
    for (int d = 1; d < 256; d <<= 1) {
        int x = (t >= d) ? sh[t - d] : 0;
        __syncthreads();
        sh[t] += x;
        __syncthreads();
    }
    int incl = sh[t];
    if (t == 255) sbase = atomicAdd(&g_total, incl);
    __syncthreads();
    if (i < n) {
        int off = sbase + incl - v;
        g_off[i] = off;
        g_end[i] = off + v;
        g_cursor[i] = off;
    }
}

// ============================================================================
// Launch 2: scatter src into CSR slots
// ============================================================================
__global__ __launch_bounds__(256)
void scatter(const int* __restrict__ src, const int* __restrict__ dst, int ne) {
    int tid = blockIdx.x * blockDim.x + threadIdx.x;
    int stride = gridDim.x * blockDim.x;
    int nv = ne >> 2;
    const int4* s4 = reinterpret_cast<const int4*>(src);
    const int4* d4 = reinterpret_cast<const int4*>(dst);
    for (int i = tid; i < nv; i += stride) {
        int4 s = __ldg(&s4[i]);
        int4 d = __ldg(&d4[i]);
        int p0 = atomicAdd(&g_cursor[d.x], 1);
        int p1 = atomicAdd(&g_cursor[d.y], 1);
        int p2 = atomicAdd(&g_cursor[d.z], 1);
        int p3 = atomicAdd(&g_cursor[d.w], 1);
        g_esrc[p0] = s.x;
        g_esrc[p1] = s.y;
        g_esrc[p2] = s.z;
        g_esrc[p3] = s.w;
    }
    for (int i = (nv << 2) + tid; i < ne; i += stride) {
        int pos = atomicAdd(&g_cursor[dst[i]], 1);
        g_esrc[pos] = src[i];
    }
}

// ============================================================================
// Gather-aggregate: TWO warps per dst node (edge range split in half).
// Within a warp: lane = e*5 + c (6 edge slots x 5 uint4 chunks of 80B row).
// Partials written with red.global.add.v4 into g_acc (36 acc + 3 den).
// ============================================================================
__global__ __launch_bounds__(256)
void gather_agg(int n_nodes) {
    int gwarp = (blockIdx.x * blockDim.x + threadIdx.x) >> 5;
    int n = gwarp >> 1;
    if (n >= n_nodes) return;
    int halfsel = gwarp & 1;
    int lane = threadIdx.x & 31;

    int e = lane / 5;        // 0..5 valid; 6 for lanes 30,31
    int c = lane - e * 5;    // 0..4
    bool laneOk = lane < 30;
    bool isEl = laneOk && (c == 4);
    int srcl = e * 5 + 4;

    int ha = (c < 2) ? 0 : (c == 2 ? 1 : 2);
    int hb = (c == 0) ? 0 : (c < 3 ? 1 : 2);

    int beg0 = g_off[n];
    int end0 = g_end[n];
    int mid = beg0 + (((end0 - beg0) + 1) >> 1);
    int beg = halfsel ? mid : beg0;
    int end = halfsel ? end0 : mid;

    float er0 = g_er[n * NH + 0];
    float er1 = g_er[n * NH + 1];
    float er2 = g_er[n * NH + 2];

    float acc[8];
#pragma unroll
    for (int i = 0; i < 8; i++) acc[i] = 0.f;
    float den0 = 0.f, den1 = 0.f, den2 = 0.f;

    for (int i = beg; i < end; i += 6) {
        int idx = i + e;
        bool act = laneOk && (idx < end);
        int s = act ? __ldg(&g_esrc[idx]) : 0;

        uint4 q = make_uint4(0, 0, 0, 0);
        if (act)
            q = __ldg(reinterpret_cast<const uint4*>(g_fe + s * FEH) + c);

        float ee0 = 0.f, ee1 = 0.f, ee2 = 0.f;
        if (isEl && act) {
            float2 e01 = __half22float2(*reinterpret_cast<__half2*>(&q.z));
            float2 e23 = __half22float2(*reinterpret_cast<__half2*>(&q.w));
            float v0 = e01.x + er0;
            float v1 = e01.y + er1;
            float v2 = e23.x + er2;
            v0 = v0 >= 0.f ? v0 : 0.2f * v0;
            v1 = v1 >= 0.f ? v1 : 0.2f * v1;
            v2 = v2 >= 0.f ? v2 : 0.2f * v2;
            ee0 = __expf(v0);
            ee1 = __expf(v1);
            ee2 = __expf(v2);
            den0 += ee0;
            den1 += ee1;
            den2 += ee2;
        }
        float w0 = __shfl_sync(FULL, ee0, srcl);
        float w1 = __shfl_sync(FULL, ee1, srcl);
        float w2 = __shfl_sync(FULL, ee2, srcl);
        float wa = (ha == 0) ? w0 : (ha == 1 ? w1 : w2);
        float wb = (hb == 0) ? w0 : (hb == 1 ? w1 : w2);
        if (c == 4) wb = 0.f;

        float2 f01 = __half22float2(*reinterpret_cast<__half2*>(&q.x));
        float2 f23 = __half22float2(*reinterpret_cast<__half2*>(&q.y));
        float2 f45 = __half22float2(*reinterpret_cast<__half2*>(&q.z));
        float2 f67 = __half22float2(*reinterpret_cast<__half2*>(&q.w));
        acc[0] += wa * f01.x;
        acc[1] += wa * f01.y;
        acc[2] += wa * f23.x;
        acc[3] += wa * f23.y;
        acc[4] += wb * f45.x;
        acc[5] += wb * f45.y;
        acc[6] += wb * f67.x;
        acc[7] += wb * f67.y;
    }

    // 6-group stride-5 reduction (hazard-free two-stage)
#pragma unroll
    for (int i = 0; i < 8; i++) {
        float t = acc[i];
        t += __shfl_down_sync(FULL, t, 15);
        float a5  = __shfl_down_sync(FULL, t, 5);
        float a10 = __shfl_down_sync(FULL, t, 10);
        acc[i] = t + a5 + a10;
    }
    {
        float t = den0;
        t += __shfl_down_sync(FULL, t, 15);
        den0 = t + __shfl_down_sync(FULL, t, 5) + __shfl_down_sync(FULL, t, 10);
    }
    {
        float t = den1;
        t += __shfl_down_sync(FULL, t, 15);
        den1 = t + __shfl_down_sync(FULL, t, 5) + __shfl_down_sync(FULL, t, 10);
    }
    {
        float t = den2;
        t += __shfl_down_sync(FULL, t, 15);
        den2 = t + __shfl_down_sync(FULL, t, 5) + __shfl_down_sync(FULL, t, 10);
    }

    // acc totals on lanes 0..4; den totals on lane 4
    float* arow = g_acc + n * ACC_S;
    if (lane < 5) {
        red_add_v4(arow + 8 * lane, acc[0], acc[1], acc[2], acc[3]);
        if (lane < 4)
            red_add_v4(arow + 8 * lane + 4, acc[4], acc[5], acc[6], acc[7]);
        else
            red_add_v4(arow + 36, den0, den1, den2, 0.f);
    }
}

// ============================================================================
// Node kernel layers 1,2: x = elu(rst + acc/den); re-zero acc row; project.
// ============================================================================
__global__ __launch_bounds__(128)
void node_prep_mid(const float* __restrict__ fc_w,
                   const float* __restrict__ a_l, const float* __restrict__ a_r,
                   const float* __restrict__ bias, int n_nodes) {
    __shared__ float sW[HID * HID];
    __shared__ float sAl[HID], sAr[HID], sB[HID];

    int tid = threadIdx.x;
    for (int i = tid; i < HID * HID; i += blockDim.x) sW[i] = fc_w[i];
    if (tid < HID) {
        sAl[tid] = a_l[tid];
        sAr[tid] = a_r[tid];
        sB[tid]  = bias[tid];
    }
    __syncthreads();

    int n = blockIdx.x * blockDim.x + tid;
    if (n >= n_nodes) return;

    // read acc row, compute inverse denominators, zero the row
    float ac[ACC_S];
    float4* ap = reinterpret_cast<float4*>(g_acc + n * ACC_S);
#pragma unroll
    for (int i = 0; i < 10; i++) {
        float4 v = ap[i];
        ac[4 * i] = v.x; ac[4 * i + 1] = v.y; ac[4 * i + 2] = v.z; ac[4 * i + 3] = v.w;
    }
#pragma unroll
    for (int i = 0; i < 10; i++)
        ap[i] = make_float4(0.f, 0.f, 0.f, 0.f);

    float inv0 = 1.0f / fmaxf(ac[36], 1e-9f);
    float inv1 = 1.0f / fmaxf(ac[37], 1e-9f);
    float inv2 = 1.0f / fmaxf(ac[38], 1e-9f);

    float x[HID];
#pragma unroll
    for (int k = 0; k < HID; k++) {
        float iv = (k < 12) ? inv0 : (k < 24 ? inv1 : inv2);
        float v = g_rst[n * HID + k] + ac[k] * iv;
        x[k] = v > 0.f ? v : expm1f(v);   // ELU
    }

    float f[HID];
#pragma unroll
    for (int j = 0; j < HID; j++) {
        float a = 0.f;
#pragma unroll
        for (int k = 0; k < HID; k++) a += x[k] * sW[k * HID + j];
        f[j] = a;
    }

#pragma unroll
    for (int j = 0; j < HID; j++)
        g_rst[n * HID + j] = x[j] + sB[j];

    float el[NH];
#pragma unroll
    for (int h = 0; h < NH; h++) {
        float l = 0.f, r = 0.f;
#pragma unroll
        for (int d = 0; d < HD; d++) {
            l += f[h * HD + d] * sAl[h * HD + d];
            r += f[h * HD + d] * sAr[h * HD + d];
        }
        el[h] = l;
        g_er[n * NH + h] = r;
    }

    unsigned u[20];
#pragma unroll
    for (int i = 0; i < 18; i++) u[i] = pack2(f[2 * i], f[2 * i + 1]);
    u[18] = pack2(el[0], el[1]);
    u[19] = pack2(el[2], 0.f);
    uint4* dp = reinterpret_cast<uint4*>(g_fe + n * FEH);
#pragma unroll
    for (int i = 0; i < 5; i++)
        dp[i] = make_uint4(u[4 * i], u[4 * i + 1], u[4 * i + 2], u[4 * i + 3]);
}

// ============================================================================
// Output: out = elu(rst + acc/den) @ out_w + out_b; reset scratch for next call
// ============================================================================
__global__ __launch_bounds__(128)
void out_proj(const float* __restrict__ out_w, const float* __restrict__ out_b,
              float* __restrict__ out, int n_nodes) {
    __shared__ float sW[HID * HID];
    __shared__ float sB[HID];
    int tid = threadIdx.x;
    for (int i = tid; i < HID * HID; i += blockDim.x) sW[i] = out_w[i];
    if (tid < HID) sB[tid] = out_b[tid];
    __syncthreads();

    int n = blockIdx.x * blockDim.x + tid;
    if (n >= n_nodes) return;

    // reset per-call scratch
    g_deg[n] = 0;
    if (n == 0) g_total = 0;

    float ac[ACC_S];
    float4* ap = reinterpret_cast<float4*>(g_acc + n * ACC_S);
#pragma unroll
    for (int i = 0; i < 10; i++) {
        float4 v = ap[i];
        ac[4 * i] = v.x; ac[4 * i + 1] = v.y; ac[4 * i + 2] = v.z; ac[4 * i + 3] = v.w;
    }
#pragma unroll
    for (int i = 0; i < 10; i++)
        ap[i] = make_float4(0.f, 0.f, 0.f, 0.f);

    float inv0 = 1.0f / fmaxf(ac[36], 1e-9f);
    float inv1 = 1.0f / fmaxf(ac[37], 1e-9f);
    float inv2 = 1.0f / fmaxf(ac[38], 1e-9f);

    float x[HID];
#pragma unroll
    for (int k = 0; k < HID; k++) {
        float iv = (k < 12) ? inv0 : (k < 24 ? inv1 : inv2);
        float v = g_rst[n * HID + k] + ac[k] * iv;
        x[k] = v > 0.f ? v : expm1f(v);
    }
#pragma unroll
    for (int j = 0; j < HID; j++) {
        float a = sB[j];
#pragma unroll
        for (int k = 0; k < HID; k++) a += x[k] * sW[k * HID + j];
        out[n * HID + j] = a;
    }
}

// ============================================================================
extern "C" void kernel_launch(void* const* d_in, const int* in_sizes, int n_in,
                              void* d_out, int out_size) {
    const float* node_features = (const float*)d_in[0];
    const int*   src           = (const int*)  d_in[1];
    const int*   dst           = (const int*)  d_in[2];
    const float* lin0_w        = (const float*)d_in[3];
    const float* lin0_b        = (const float*)d_in[4];
    const float* fc_w          = (const float*)d_in[5];
    const float* attn_l        = (const float*)d_in[6];
    const float* attn_r        = (const float*)d_in[7];
    const float* gat_bias      = (const float*)d_in[8];
    const float* out_w         = (const float*)d_in[9];
    const float* out_b         = (const float*)d_in[10];

    int n  = in_sizes[0] / HID;
    int ne = in_sizes[1];

    int nb_np  = (n + 255) / 256;          // node blocks (256 thr)
    int nb_n   = (n + 127) / 128;          // node blocks (128 thr)
    int nb_s   = 148 * 4;                  // hist/scatter grid-stride blocks
    int nb_g   = (n * 2 * 32 + 255) / 256; // 2 warps per node

    // 0: fused layer-0 node_prep + degree histogram
    prep0_hist<<<nb_np + nb_s, 256>>>(node_features, lin0_w, lin0_b,
                                      fc_w, attn_l, attn_r, gat_bias,
                                      dst, n, ne, nb_np);
    // 1: single-pass scan
    scan_fused<<<nb_np, 256>>>(n);
    // 2: scatter
    scatter<<<nb_s, 256>>>(src, dst, ne);
    // 3: gather layer 0  (profiled launch)
    gather_agg<<<nb_g, 256>>>(n);

    for (int l = 1; l < 3; l++) {
        node_prep_mid<<<nb_n, 128>>>(fc_w + l * HID * HID,
                                     attn_l + l * HID, attn_r + l * HID,
                                     gat_bias + l * HID, n);
        gather_agg<<<nb_g, 256>>>(n);
    }
    out_proj<<<nb_n, 128>>>(out_w, out_b, (float*)d_out, n);
}

// round 8
// speedup vs baseline: 1.0941x; 1.0941x over previous
#include <cuda_runtime.h>
#include <cuda_bf16.h>
#include <cuda_fp16.h>

#define NN 100000
#define NE 3200000
#define HID 36
#define NH 3
#define HD 12
#define FEH 48           // packed fp16 row stride in halves: 36 feat + 3 el + pad = 96B
#define ESRC_CAP (NE + 5 * NN + 64)
#define FULL 0xffffffffu

// ---- persistent scratch ----
__device__ __align__(128) __half g_fe[(NN + 1) * FEH]; // row NN = pad row (feat 0, el -300)
__device__ float g_er[NN * NH];
__device__ float g_rst[NN * HID];    // x + bias (+ msg added by gather)
__device__ int   g_deg[NN];          // zero-init; out_proj re-zeroes for next call
__device__ int   g_off[NN];
__device__ int   g_end[NN];          // padded end (multiple of 6 per node)
__device__ int   g_cursor[NN];
__device__ int   g_esrc[ESRC_CAP];
__device__ int   g_total;            // zero-init; out_proj re-zeroes

__device__ __forceinline__ unsigned pack2(float a, float b) {
    __half2 h = __floats2half2_rn(a, b);
    return *reinterpret_cast<unsigned*>(&h);
}

__device__ __forceinline__ unsigned long long f32x2_pack(float lo, float hi) {
    unsigned long long r;
    asm("mov.b64 %0, {%1, %2};" : "=l"(r) : "f"(lo), "f"(hi));
    return r;
}
__device__ __forceinline__ unsigned long long f32x2_fma(unsigned long long a,
                                                        unsigned long long b,
                                                        unsigned long long c) {
    unsigned long long d;
    asm("fma.rn.f32x2 %0, %1, %2, %3;" : "=l"(d) : "l"(a), "l"(b), "l"(c));
    return d;
}
__device__ __forceinline__ void f32x2_unpack(unsigned long long v, float& lo, float& hi) {
    asm("mov.b64 {%0, %1}, %2;" : "=f"(lo), "=f"(hi) : "l"(v));
}

// ============================================================================
// Launch 0: fused node_prep<layer0> (blocks [0,np_blocks)) + hist (rest).
// ============================================================================
__global__ __launch_bounds__(256)
void prep0_hist(const float* __restrict__ in,
                const float* __restrict__ lin0_w, const float* __restrict__ lin0_b,
                const float* __restrict__ fc_w,
                const float* __restrict__ a_l, const float* __restrict__ a_r,
                const float* __restrict__ bias,
                const int* __restrict__ dst,
                int n_nodes, int ne, int np_blocks) {
    if (blockIdx.x >= np_blocks) {
        int bid = blockIdx.x - np_blocks;
        int nb  = gridDim.x - np_blocks;
        int tid = bid * 256 + threadIdx.x;
        int stride = nb * 256;
        int nv = ne >> 2;
        const int4* d4 = reinterpret_cast<const int4*>(dst);
        for (int i = tid; i < nv; i += stride) {
            int4 d = __ldg(&d4[i]);
            atomicAdd(&g_deg[d.x], 1);
            atomicAdd(&g_deg[d.y], 1);
            atomicAdd(&g_deg[d.z], 1);
            atomicAdd(&g_deg[d.w], 1);
        }
        for (int i = (nv << 2) + tid; i < ne; i += stride)
            atomicAdd(&g_deg[dst[i]], 1);
        return;
    }

    __shared__ float sW[HID * HID];
    __shared__ float sW0[HID * HID];
    __shared__ float sAl[HID], sAr[HID], sB[HID], sB0[HID];

    int tid = threadIdx.x;
    for (int i = tid; i < HID * HID; i += 256) {
        sW[i]  = fc_w[i];
        sW0[i] = lin0_w[i];
    }
    if (tid < HID) {
        sAl[tid] = a_l[tid];
        sAr[tid] = a_r[tid];
        sB[tid]  = bias[tid];
        sB0[tid] = lin0_b[tid];
    }
    __syncthreads();

    int n = blockIdx.x * 256 + tid;
    if (n >= n_nodes) return;

    float nf[HID], x[HID];
#pragma unroll
    for (int k = 0; k < HID; k++) nf[k] = in[n * HID + k];
#pragma unroll
    for (int j = 0; j < HID; j++) {
        float a = sB0[j];
#pragma unroll
        for (int k = 0; k < HID; k++) a += nf[k] * sW0[k * HID + j];
        x[j] = a;
    }

    float f[HID];
#pragma unroll
    for (int j = 0; j < HID; j++) {
        float a = 0.f;
#pragma unroll
        for (int k = 0; k < HID; k++) a += x[k] * sW[k * HID + j];
        f[j] = a;
    }

#pragma unroll
    for (int j = 0; j < HID; j++)
        g_rst[n * HID + j] = x[j] + sB[j];

    float el[NH];
#pragma unroll
    for (int h = 0; h < NH; h++) {
        float l = 0.f, r = 0.f;
#pragma unroll
        for (int d = 0; d < HD; d++) {
            l += f[h * HD + d] * sAl[h * HD + d];
            r += f[h * HD + d] * sAr[h * HD + d];
        }
        el[h] = l;
        g_er[n * NH + h] = r;
    }

    unsigned u[20];
#pragma unroll
    for (int i = 0; i < 18; i++) u[i] = pack2(f[2 * i], f[2 * i + 1]);
    u[18] = pack2(el[0], el[1]);
    u[19] = pack2(el[2], 0.f);
    uint4* dp = reinterpret_cast<uint4*>(g_fe + n * FEH);
#pragma unroll
    for (int i = 0; i < 5; i++)
        dp[i] = make_uint4(u[4 * i], u[4 * i + 1], u[4 * i + 2], u[4 * i + 3]);
}

// ============================================================================
// Launch 1: single-pass scan over PADDED degrees (ceil to multiple of 6);
// fills pad slots with src = NN (zero node). Also refreshes pad row's el.
// ============================================================================
__global__ __launch_bounds__(256)
void scan_fused(int n) {
    __shared__ int sh[256];
    __shared__ int sbase;
    int t = threadIdx.x;
    int i = blockIdx.x * 256 + t;
    int deg = (i < n) ? g_deg[i] : 0;
    int pd = ((deg + 5) / 6) * 6;
    sh[t] = pd;
    __syncthreads();
    for (int d = 1; d < 256; d <<= 1) {
        int x = (t >= d) ? sh[t - d] : 0;
        __syncthreads();
        sh[t] += x;
        __syncthreads();
    }
    int incl = sh[t];
    if (t == 255) sbase = atomicAdd(&g_total, incl);
    __syncthreads();
    if (i < n) {
        int off = sbase + incl - pd;
        g_off[i] = off;
        g_end[i] = off + pd;
        g_cursor[i] = off;
        for (int j = off + deg; j < off + pd; j++)
            g_esrc[j] = NN;                 // pad slots -> zero node
    }
    if (blockIdx.x == 0 && t == 0) {
        __half neg = __float2half(-300.f);  // exp(leaky(-300+er)) == 0
        g_fe[NN * FEH + 36] = neg;
        g_fe[NN * FEH + 37] = neg;
        g_fe[NN * FEH + 38] = neg;
    }
}

// ============================================================================
// Launch 2: scatter src into CSR slots
// ============================================================================
__global__ __launch_bounds__(256)
void scatter(const int* __restrict__ src, const int* __restrict__ dst, int ne) {
    int tid = blockIdx.x * blockDim.x + threadIdx.x;
    int stride = gridDim.x * blockDim.x;
    int nv = ne >> 2;
    const int4* s4 = reinterpret_cast<const int4*>(src);
    const int4* d4 = reinterpret_cast<const int4*>(dst);
    for (int i = tid; i < nv; i += stride) {
        int4 s = __ldg(&s4[i]);
        int4 d = __ldg(&d4[i]);
        int p0 = atomicAdd(&g_cursor[d.x], 1);
        int p1 = atomicAdd(&g_cursor[d.y], 1);
        int p2 = atomicAdd(&g_cursor[d.z], 1);
        int p3 = atomicAdd(&g_cursor[d.w], 1);
        g_esrc[p0] = s.x;
        g_esrc[p1] = s.y;
        g_esrc[p2] = s.z;
        g_esrc[p3] = s.w;
    }
    for (int i = (nv << 2) + tid; i < ne; i += stride) {
        int pos = atomicAdd(&g_cursor[dst[i]], 1);
        g_esrc[pos] = src[i];
    }
}

// ============================================================================
// Gather-aggregate: one warp per dst node, 6 edges/iter, NO bounds logic
// (ranges padded to multiples of 6; pads hit the zero node).
// lane = e*5 + c (e<6 edge slot, c<5 uint4 chunk of 80B packed fp16 row).
// Packed f32x2 FMA accumulation; direct g_rst writeback.
// ============================================================================
__global__ __launch_bounds__(256)
void gather_agg(int n_nodes) {
    int warp = (blockIdx.x * blockDim.x + threadIdx.x) >> 5;
    if (warp >= n_nodes) return;
    int lane = threadIdx.x & 31;
    int n = warp;

    int e = lane / 5;        // 0..5 valid; 6 for lanes 30,31 (masked to zero node)
    int c = lane - e * 5;    // 0..4
    bool laneOk = lane < 30;
    bool isEl = laneOk && (c == 4);
    int srcl = e * 5 + 4;

    int ha = (c < 2) ? 0 : (c == 2 ? 1 : 2);
    int hb = (c == 0) ? 0 : (c < 3 ? 1 : 2);

    int beg = g_off[n];
    int end = g_end[n];      // multiple of 6 past beg

    float er0 = g_er[n * NH + 0];
    float er1 = g_er[n * NH + 1];
    float er2 = g_er[n * NH + 2];

    unsigned long long a01 = 0, a23 = 0, a45 = 0, a67 = 0;  // f32x2 pairs (0 bits = 0.0f)
    float den0 = 0.f, den1 = 0.f, den2 = 0.f;

    for (int i = beg; i < end; i += 6) {
        int s = NN;
        if (laneOk) s = __ldg(&g_esrc[i + e]);
        uint4 q = __ldg(reinterpret_cast<const uint4*>(g_fe + s * FEH) + c);

        float ee0 = 0.f, ee1 = 0.f, ee2 = 0.f;
        if (isEl) {
            float2 e01 = __half22float2(*reinterpret_cast<__half2*>(&q.z));
            float2 e23 = __half22float2(*reinterpret_cast<__half2*>(&q.w));
            float v0 = e01.x + er0;
            float v1 = e01.y + er1;
            float v2 = e23.x + er2;
            v0 = v0 >= 0.f ? v0 : 0.2f * v0;
            v1 = v1 >= 0.f ? v1 : 0.2f * v1;
            v2 = v2 >= 0.f ? v2 : 0.2f * v2;
            ee0 = __expf(v0);
            ee1 = __expf(v1);
            ee2 = __expf(v2);
            den0 += ee0;
            den1 += ee1;
            den2 += ee2;
        }
        float w0 = __shfl_sync(FULL, ee0, srcl);
        float w1 = __shfl_sync(FULL, ee1, srcl);
        float w2 = __shfl_sync(FULL, ee2, srcl);
        float wa = (ha == 0) ? w0 : (ha == 1 ? w1 : w2);
        float wb = (hb == 0) ? w0 : (hb == 1 ? w1 : w2);
        if (c == 4) wb = 0.f;   // chunk 4's upper halves are el/pad, not feat

        unsigned long long wa2 = f32x2_pack(wa, wa);
        unsigned long long wb2 = f32x2_pack(wb, wb);
        float2 f01 = __half22float2(*reinterpret_cast<__half2*>(&q.x));
        float2 f23 = __half22float2(*reinterpret_cast<__half2*>(&q.y));
        float2 f45 = __half22float2(*reinterpret_cast<__half2*>(&q.z));
        float2 f67 = __half22float2(*reinterpret_cast<__half2*>(&q.w));
        a01 = f32x2_fma(f32x2_pack(f01.x, f01.y), wa2, a01);
        a23 = f32x2_fma(f32x2_pack(f23.x, f23.y), wa2, a23);
        a45 = f32x2_fma(f32x2_pack(f45.x, f45.y), wb2, a45);
        a67 = f32x2_fma(f32x2_pack(f67.x, f67.y), wb2, a67);
    }

    float acc[8];
    f32x2_unpack(a01, acc[0], acc[1]);
    f32x2_unpack(a23, acc[2], acc[3]);
    f32x2_unpack(a45, acc[4], acc[5]);
    f32x2_unpack(a67, acc[6], acc[7]);

    // 6-group stride-5 reduction (hazard-free two-stage)
#pragma unroll
    for (int i = 0; i < 8; i++) {
        float t = acc[i];
        t += __shfl_down_sync(FULL, t, 15);
        float a5  = __shfl_down_sync(FULL, t, 5);
        float a10 = __shfl_down_sync(FULL, t, 10);
        acc[i] = t + a5 + a10;
    }
    {
        float t = den0;
        t += __shfl_down_sync(FULL, t, 15);
        den0 = t + __shfl_down_sync(FULL, t, 5) + __shfl_down_sync(FULL, t, 10);
    }
    {
        float t = den1;
        t += __shfl_down_sync(FULL, t, 15);
        den1 = t + __shfl_down_sync(FULL, t, 5) + __shfl_down_sync(FULL, t, 10);
    }
    {
        float t = den2;
        t += __shfl_down_sync(FULL, t, 15);
        den2 = t + __shfl_down_sync(FULL, t, 5) + __shfl_down_sync(FULL, t, 10);
    }

    float d0 = __shfl_sync(FULL, den0, 4);
    float d1 = __shfl_sync(FULL, den1, 4);
    float d2 = __shfl_sync(FULL, den2, 4);

    if (lane < 5) {
        float inv0 = 1.0f / fmaxf(d0, 1e-9f);
        float inv1 = 1.0f / fmaxf(d1, 1e-9f);
        float inv2 = 1.0f / fmaxf(d2, 1e-9f);
        float va = (ha == 0) ? inv0 : (ha == 1 ? inv1 : inv2);
        float vb = (hb == 0) ? inv0 : (hb == 1 ? inv1 : inv2);

        float* rp = g_rst + n * HID + 8 * lane;
        float4 r0 = *reinterpret_cast<float4*>(rp);
        r0.x += acc[0] * va;
        r0.y += acc[1] * va;
        r0.z += acc[2] * va;
        r0.w += acc[3] * va;
        *reinterpret_cast<float4*>(rp) = r0;
        if (lane < 4) {
            float4 r1 = *reinterpret_cast<float4*>(rp + 4);
            r1.x += acc[4] * vb;
            r1.y += acc[5] * vb;
            r1.z += acc[6] * vb;
            r1.w += acc[7] * vb;
            *reinterpret_cast<float4*>(rp + 4) = r1;
        }
    }
}

// ============================================================================
// Node kernel layers 1,2: x = elu(rst); project; write fe/er; rst = x + bias.
// ============================================================================
__global__ __launch_bounds__(128)
void node_prep_mid(const float* __restrict__ fc_w,
                   const float* __restrict__ a_l, const float* __restrict__ a_r,
                   const float* __restrict__ bias, int n_nodes) {
    __shared__ float sW[HID * HID];
    __shared__ float sAl[HID], sAr[HID], sB[HID];

    int tid = threadIdx.x;
    for (int i = tid; i < HID * HID; i += blockDim.x) sW[i] = fc_w[i];
    if (tid < HID) {
        sAl[tid] = a_l[tid];
        sAr[tid] = a_r[tid];
        sB[tid]  = bias[tid];
    }
    __syncthreads();

    int n = blockIdx.x * blockDim.x + tid;
    if (n >= n_nodes) return;

    float x[HID];
#pragma unroll
    for (int k = 0; k < HID; k++) {
        float v = g_rst[n * HID + k];
        x[k] = v > 0.f ? v : expm1f(v);   // ELU
    }

    float f[HID];
#pragma unroll
    for (int j = 0; j < HID; j++) {
        float a = 0.f;
#pragma unroll
        for (int k = 0; k < HID; k++) a += x[k] * sW[k * HID + j];
        f[j] = a;
    }

#pragma unroll
    for (int j = 0; j < HID; j++)
        g_rst[n * HID + j] = x[j] + sB[j];

    float el[NH];
#pragma unroll
    for (int h = 0; h < NH; h++) {
        float l = 0.f, r = 0.f;
#pragma unroll
        for (int d = 0; d < HD; d++) {
            l += f[h * HD + d] * sAl[h * HD + d];
            r += f[h * HD + d] * sAr[h * HD + d];
        }
        el[h] = l;
        g_er[n * NH + h] = r;
    }

    unsigned u[20];
#pragma unroll
    for (int i = 0; i < 18; i++) u[i] = pack2(f[2 * i], f[2 * i + 1]);
    u[18] = pack2(el[0], el[1]);
    u[19] = pack2(el[2], 0.f);
    uint4* dp = reinterpret_cast<uint4*>(g_fe + n * FEH);
#pragma unroll
    for (int i = 0; i < 5; i++)
        dp[i] = make_uint4(u[4 * i], u[4 * i + 1], u[4 * i + 2], u[4 * i + 3]);
}

// ============================================================================
// Output: out = elu(rst) @ out_w + out_b; reset scratch for next call
// ============================================================================
__global__ __launch_bounds__(128)
void out_proj(const float* __restrict__ out_w, const float* __restrict__ out_b,
              float* __restrict__ out, int n_nodes) {
    __shared__ float sW[HID * HID];
    __shared__ float sB[HID];
    int tid = threadIdx.x;
    for (int i = tid; i < HID * HID; i += blockDim.x) sW[i] = out_w[i];
    if (tid < HID) sB[tid] = out_b[tid];
    __syncthreads();

    int n = blockIdx.x * blockDim.x + tid;
    if (n >= n_nodes) return;

    g_deg[n] = 0;
    if (n == 0) g_total = 0;

    float x[HID];
#pragma unroll
    for (int k = 0; k < HID; k++) {
        float v = g_rst[n * HID + k];
        x[k] = v > 0.f ? v : expm1f(v);
    }
#pragma unroll
    for (int j = 0; j < HID; j++) {
        float a = sB[j];
#pragma unroll
        for (int k = 0; k < HID; k++) a += x[k] * sW[k * HID + j];
        out[n * HID + j] = a;
    }
}

// ============================================================================
extern "C" void kernel_launch(void* const* d_in, const int* in_sizes, int n_in,
                              void* d_out, int out_size) {
    const float* node_features = (const float*)d_in[0];
    const int*   src           = (const int*)  d_in[1];
    const int*   dst           = (const int*)  d_in[2];
    const float* lin0_w        = (const float*)d_in[3];
    const float* lin0_b        = (const float*)d_in[4];
    const float* fc_w          = (const float*)d_in[5];
    const float* attn_l        = (const float*)d_in[6];
    const float* attn_r        = (const float*)d_in[7];
    const float* gat_bias      = (const float*)d_in[8];
    const float* out_w         = (const float*)d_in[9];
    const float* out_b         = (const float*)d_in[10];

    int n  = in_sizes[0] / HID;
    int ne = in_sizes[1];

    int nb_np  = (n + 255) / 256;
    int nb_n   = (n + 127) / 128;
    int nb_s   = 148 * 4;
    int nb_g   = (n * 32 + 255) / 256;   // one warp per node

    // 0: fused layer-0 node_prep + degree histogram
    prep0_hist<<<nb_np + nb_s, 256>>>(node_features, lin0_w, lin0_b,
                                      fc_w, attn_l, attn_r, gat_bias,
                                      dst, n, ne, nb_np);
    // 1: padded scan + pad fill
    scan_fused<<<nb_np, 256>>>(n);
    // 2: scatter
    scatter<<<nb_s, 256>>>(src, dst, ne);
    // 3: gather layer 0  (profiled launch)
    gather_agg<<<nb_g, 256>>>(n);

    for (int l = 1; l < 3; l++) {
        node_prep_mid<<<nb_n, 128>>>(fc_w + l * HID * HID,
                                     attn_l + l * HID, attn_r + l * HID,
                                     gat_bias + l * HID, n);
        gather_agg<<<nb_g, 256>>>(n);
    }
    out_proj<<<nb_n, 128>>>(out_w, out_b, (float*)d_out, n);
}